// round 6
// baseline (speedup 1.0000x reference)
#include <cuda_runtime.h>
#include <cuda_fp16.h>
#include <math.h>
#include <stdint.h>

#define BB 32
#define SS 4096
#define VD 512
#define HD 512
#define QD 512
#define CTX_SIZE (BB*VD)
#define CSPLIT 32

// -------- scratch (no allocation allowed) --------
__device__ float  g_qp[BB*HD];
__device__ float  g_scores[BB*SS];
__device__ float  g_cpart[CSPLIT*BB*VD];
__device__ __half g_WkT[HD*VD];   // [h][v] fp16 (B operand, K-major "col" layout)

// ---------------- helpers ----------------
__device__ __forceinline__ uint32_t smem_u32(const void* p) {
    uint32_t a;
    asm("{ .reg .u64 t; cvta.to.shared.u64 t, %1; cvt.u32.u64 %0, t; }"
        : "=r"(a) : "l"(p));
    return a;
}
__device__ __forceinline__ void ldsm4(uint32_t* r, uint32_t addr) {
    asm volatile("ldmatrix.sync.aligned.m8n8.x4.shared.b16 {%0,%1,%2,%3}, [%4];"
        : "=r"(r[0]), "=r"(r[1]), "=r"(r[2]), "=r"(r[3]) : "r"(addr));
}
__device__ __forceinline__ void mma16816(float* d, const uint32_t* a, const uint32_t* b) {
    asm volatile("mma.sync.aligned.m16n8k16.row.col.f32.f16.f16.f32 "
        "{%0,%1,%2,%3}, {%4,%5,%6,%7}, {%8,%9}, {%0,%1,%2,%3};"
        : "+f"(d[0]), "+f"(d[1]), "+f"(d[2]), "+f"(d[3])
        : "r"(a[0]), "r"(a[1]), "r"(a[2]), "r"(a[3]), "r"(b[0]), "r"(b[1]));
}
__device__ __forceinline__ float tanha(float x) {
    float y;
    asm("tanh.approx.f32 %0, %1;" : "=f"(y) : "f"(x));
    return y;
}
__device__ __forceinline__ void cp16(uint32_t dst, const void* src) {
    asm volatile("cp.async.cg.shared.global [%0], [%1], 16;"
                 :: "r"(dst), "l"(src) : "memory");
}
#define CP_COMMIT() asm volatile("cp.async.commit_group;" ::: "memory")
#define CP_WAIT(n)  asm volatile("cp.async.wait_group %0;" :: "n"(n) : "memory")

// ---------------- Kernel 1: qp[b,h] = query[b]·Wq[:,h] + bq[h] ----------------
__global__ void qp_kernel(const float* __restrict__ query,
                          const float* __restrict__ Wq,
                          const float* __restrict__ bq) {
    int b = blockIdx.x;
    int h = threadIdx.x;              // 512
    __shared__ float qs[QD];
    qs[h] = query[b*QD + h];
    __syncthreads();
    float acc = 0.f;
    #pragma unroll 8
    for (int v = 0; v < QD; v++) acc += qs[v] * Wq[v*HD + h];
    g_qp[b*HD + h] = acc + bq[h];
}

// ---------------- Kernel 1b: WkT[h][v] = fp16(Wk[v][h]) ----------------
__global__ void wkt_kernel(const float* __restrict__ Wk) {
    int h = blockIdx.x;
    int v = threadIdx.x;              // 512
    g_WkT[h*VD + v] = __float2half_rn(Wk[v*HD + h]);
}

// ---------------- Kernel 2: mma.sync score GEMM, cp.async pipelined B ---------
// CTA: 128 rows. A[128x512] fp16 resident in smem (pad 520).
// 16 h-tiles of 32, B double-buffered via cp.async.cg (no conversion needed).
#define APAD 520
#define OFF_A   0
#define OFF_B0  133120
#define OFF_B1  166400
#define OFF_QP  199680
#define OFF_WO  201728
#define OFF_RED 203776
#define SMEM_TOTAL (204288 + 256)

__device__ __forceinline__ void prefetch_b(uint32_t bbase, int t, int tid) {
    const __half* src = g_WkT + (size_t)t * 32 * VD;
    #pragma unroll
    for (int it = 0; it < 8; it++) {
        int i = tid + it*256;         // 0..2047
        int n = i >> 6;               // 0..31 (row within tile)
        int g = i & 63;               // 16B chunk within row
        cp16(bbase + (uint32_t)(n*APAD + g*8)*2, src + (size_t)n*VD + g*8);
    }
}

__global__ __launch_bounds__(256, 1)
void score_mma_kernel(const float* __restrict__ value,
                      const float* __restrict__ Wo,
                      const float* __restrict__ bo) {
    extern __shared__ char sm[];
    const uint32_t sbase = smem_u32(sm);
    const int tid = threadIdx.x;
    const int L   = tid & 31;
    const int wid = tid >> 5;
    const int mw  = wid & 3;          // M-warp: rows mw*32..+31
    const int nw  = wid >> 2;         // N-warp: h-cols nw*16..+15 within tile
    const int b   = blockIdx.x >> 5;
    const size_t row0 = (size_t)blockIdx.x * 128;

    __half* As  = (__half*)(sm + OFF_A);
    float* qp_s = (float*)(sm + OFF_QP);
    float* wo_s = (float*)(sm + OFF_WO);
    float* red  = (float*)(sm + OFF_RED);

    // prefetch B tile 0 first so it overlaps with A staging
    prefetch_b(sbase + OFF_B0, 0, tid);
    CP_COMMIT();

    // ---- stage A: value[row0..+127][0..511] f32 -> fp16, pad 520 ----
    {
        const float* vsrc = value + row0 * VD;
        #pragma unroll
        for (int it = 0; it < 64; it++) {
            int i  = tid + it*256;            // 0..16383
            int r  = i >> 7;
            int f4 = i & 127;
            float4 f = *(const float4*)(vsrc + (size_t)r*VD + f4*4);
            __half2 h0 = __floats2half2_rn(f.x, f.y);
            __half2 h1 = __floats2half2_rn(f.z, f.w);
            *(uint2*)(As + r*APAD + f4*4) =
                make_uint2(*(uint32_t*)&h0, *(uint32_t*)&h1);
        }
    }
    for (int i = tid; i < HD; i += 256) {
        qp_s[i] = g_qp[b*HD + i];
        wo_s[i] = Wo[i];
    }
    if (tid < 128) red[tid] = 0.f;

    // ldmatrix lane addresses (bytes)
    const uint32_t aAddr = sbase + OFF_A +
        (uint32_t)(((mw*32 + (L & 15))*APAD + (L >> 4)*8) * 2);
    const uint32_t bLane =
        (uint32_t)(((nw*16 + (L & 7) + ((L >> 4) << 3))*APAD + ((L >> 3) & 1)*8) * 2);
    const uint32_t bAddr0 = sbase + OFF_B0 + bLane;
    const uint32_t bAddr1 = sbase + OFF_B1 + bLane;

    float sp[4] = {0.f, 0.f, 0.f, 0.f};

    for (int t = 0; t < 16; t++) {
        if (t < 15) {
            prefetch_b(sbase + ((t & 1) ? OFF_B0 : OFF_B1), t + 1, tid);
            CP_COMMIT();
            CP_WAIT(1);               // tile t complete, t+1 in flight
        } else {
            CP_WAIT(0);
        }
        __syncthreads();

        const uint32_t bAddr = (t & 1) ? bAddr1 : bAddr0;

        float acc[2][2][4];
        #pragma unroll
        for (int mi = 0; mi < 2; mi++)
            #pragma unroll
            for (int ni = 0; ni < 2; ni++)
                #pragma unroll
                for (int j = 0; j < 4; j++) acc[mi][ni][j] = 0.f;

        #pragma unroll 8
        for (int ks = 0; ks < 32; ks++) {
            const uint32_t kb = ks * 32;      // k16 step = 32 bytes
            uint32_t a0[4], a1[4], bf[4];
            ldsm4(a0, aAddr + kb);
            ldsm4(a1, aAddr + 16*APAD*2 + kb);
            ldsm4(bf, bAddr + kb);
            mma16816(acc[0][0], a0, bf + 0);
            mma16816(acc[0][1], a0, bf + 2);
            mma16816(acc[1][0], a1, bf + 0);
            mma16816(acc[1][1], a1, bf + 2);
        }

        // epilogue: sp += Wo[h] * tanh(acc + qp[h])
        #pragma unroll
        for (int ni = 0; ni < 2; ni++) {
            const int hb = t*32 + nw*16 + ni*8 + 2*(L & 3);
            const float qp0 = qp_s[hb],  qp1 = qp_s[hb + 1];
            const float wo0 = wo_s[hb],  wo1 = wo_s[hb + 1];
            #pragma unroll
            for (int mi = 0; mi < 2; mi++) {
                float t0 = tanha(acc[mi][ni][0] + qp0);
                float t1 = tanha(acc[mi][ni][1] + qp1);
                float t2 = tanha(acc[mi][ni][2] + qp0);
                float t3 = tanha(acc[mi][ni][3] + qp1);
                sp[mi*2 + 0] += wo0*t0 + wo1*t1;   // row mw*32 + mi*16 + L/4
                sp[mi*2 + 1] += wo0*t2 + wo1*t3;   // + 8
            }
        }
        __syncthreads();              // protect buf before next prefetch
    }

    #pragma unroll
    for (int i = 0; i < 4; i++) {
        sp[i] += __shfl_xor_sync(0xffffffffu, sp[i], 1);
        sp[i] += __shfl_xor_sync(0xffffffffu, sp[i], 2);
    }
    if ((L & 3) == 0) {
        const int mr = mw*32 + (L >> 2);
        atomicAdd(&red[mr +  0], sp[0]);
        atomicAdd(&red[mr +  8], sp[1]);
        atomicAdd(&red[mr + 16], sp[2]);
        atomicAdd(&red[mr + 24], sp[3]);
    }
    __syncthreads();
    if (tid < 128)
        g_scores[row0 + tid] = red[tid] + bo[0];
}

// ---------------- Kernel 3: masked softmax, 512 thr, register-resident --------
__global__ __launch_bounds__(512)
void softmax_kernel(const int* __restrict__ mask,
                    float* __restrict__ att_out) {
    const int b = blockIdx.x;
    const int tid = threadIdx.x;      // 512
    const int L = tid & 31, w = tid >> 5;
    __shared__ float sred[16];

    float v[8];
    float m = -3.0e38f;
    #pragma unroll
    for (int i = 0; i < 8; i++) {
        int s = tid + i*512;
        float sc = (mask[b*SS + s] != 0) ? g_scores[b*SS + s] : -1e9f;
        v[i] = sc;
        m = fmaxf(m, sc);
    }
    #pragma unroll
    for (int off = 16; off > 0; off >>= 1)
        m = fmaxf(m, __shfl_xor_sync(0xffffffffu, m, off));
    if (L == 0) sred[w] = m;
    __syncthreads();
    if (w == 0) {
        float x = (L < 16) ? sred[L] : -3.0e38f;
        #pragma unroll
        for (int off = 8; off > 0; off >>= 1)
            x = fmaxf(x, __shfl_xor_sync(0xffffffffu, x, off));
        if (L == 0) sred[0] = x;
    }
    __syncthreads();
    m = sred[0];
    __syncthreads();

    float sum = 0.f;
    #pragma unroll
    for (int i = 0; i < 8; i++) {
        v[i] = expf(v[i] - m);
        sum += v[i];
    }
    #pragma unroll
    for (int off = 16; off > 0; off >>= 1)
        sum += __shfl_xor_sync(0xffffffffu, sum, off);
    if (L == 0) sred[w] = sum;
    __syncthreads();
    if (w == 0) {
        float x = (L < 16) ? sred[L] : 0.f;
        #pragma unroll
        for (int off = 8; off > 0; off >>= 1)
            x += __shfl_xor_sync(0xffffffffu, x, off);
        if (L == 0) sred[0] = x;
    }
    __syncthreads();
    const float inv = 1.f / sred[0];

    #pragma unroll
    for (int i = 0; i < 8; i++)
        att_out[b*SS + tid + i*512] = v[i] * inv;
}

// ---------------- Kernel 4: ctx partials ----------------
__global__ __launch_bounds__(128)
void ctx_part_kernel(const float* __restrict__ value,
                     const float* __restrict__ att) {
    __shared__ float atts[SS / CSPLIT];          // 128
    const int b = blockIdx.y, sc = blockIdx.x, t = threadIdx.x;
    const int s0 = sc * (SS / CSPLIT);

    atts[t] = att[b*SS + s0 + t];
    __syncthreads();

    const float* vb = value + ((size_t)(b*SS + s0))*VD + t*4;
    float ax = 0.f, ay = 0.f, az = 0.f, aw = 0.f;
    #pragma unroll 8
    for (int s = 0; s < SS / CSPLIT; s++) {
        float a = atts[s];
        float4 v4 = *(const float4*)(vb + (size_t)s*VD);
        ax = fmaf(a, v4.x, ax); ay = fmaf(a, v4.y, ay);
        az = fmaf(a, v4.z, az); aw = fmaf(a, v4.w, aw);
    }
    *(float4*)&g_cpart[((size_t)sc*BB + b)*VD + t*4] =
        make_float4(ax, ay, az, aw);
}

// ---------------- Kernel 5: reduce partials -> ctx ----------------
__global__ void ctx_reduce_kernel(float* __restrict__ ctx) {
    const int idx = blockIdx.x * 256 + threadIdx.x;  // 0..BB*VD-1
    float acc = 0.f;
    #pragma unroll
    for (int p = 0; p < CSPLIT; p++)
        acc += g_cpart[(size_t)p*(BB*VD) + idx];
    ctx[idx] = acc;
}

extern "C" void kernel_launch(void* const* d_in, const int* in_sizes, int n_in,
                              void* d_out, int out_size) {
    const float* query = (const float*)d_in[0];
    const float* value = (const float*)d_in[1];
    const int*   mask  = (const int*)d_in[2];   // bool promoted to int32
    const float* Wk    = (const float*)d_in[3];
    const float* Wq    = (const float*)d_in[4];
    const float* bq    = (const float*)d_in[5];
    const float* Wo    = (const float*)d_in[6];
    const float* bo    = (const float*)d_in[7];

    float* out = (float*)d_out;
    float* ctx = out;                 // [B, VD]
    float* att = out + CTX_SIZE;      // [B, S]

    qp_kernel<<<BB, 512>>>(query, Wq, bq);
    wkt_kernel<<<HD, VD>>>(Wk);

    cudaFuncSetAttribute(score_mma_kernel,
                         cudaFuncAttributeMaxDynamicSharedMemorySize, SMEM_TOTAL);
    score_mma_kernel<<<(BB*SS)/128, 256, SMEM_TOTAL>>>(value, Wo, bo);

    softmax_kernel<<<BB, 512>>>(mask, att);

    ctx_part_kernel<<<dim3(CSPLIT, BB), 128>>>(value, att);
    ctx_reduce_kernel<<<(BB*VD)/256, 256>>>(ctx);
}

// round 7
// speedup vs baseline: 1.0860x; 1.0860x over previous
#include <cuda_runtime.h>
#include <cuda_fp16.h>
#include <math.h>
#include <stdint.h>

#define BB 32
#define SS 4096
#define VD 512
#define HD 512
#define QD 512
#define CTX_SIZE (BB*VD)
#define CSPLIT 32

// -------- scratch (no allocation allowed) --------
__device__ float  g_qp[BB*HD];
__device__ float  g_scores[BB*SS];
__device__ float  g_cpart[CSPLIT*BB*VD];
__device__ __half g_WkT[HD*VD];   // [h][v] fp16 (B operand, K-major "col" layout)

// ---------------- helpers ----------------
__device__ __forceinline__ uint32_t smem_u32(const void* p) {
    uint32_t a;
    asm("{ .reg .u64 t; cvta.to.shared.u64 t, %1; cvt.u32.u64 %0, t; }"
        : "=r"(a) : "l"(p));
    return a;
}
__device__ __forceinline__ void ldsm4(uint32_t* r, uint32_t addr) {
    asm volatile("ldmatrix.sync.aligned.m8n8.x4.shared.b16 {%0,%1,%2,%3}, [%4];"
        : "=r"(r[0]), "=r"(r[1]), "=r"(r[2]), "=r"(r[3]) : "r"(addr));
}
__device__ __forceinline__ void mma16816(float* d, const uint32_t* a, const uint32_t* b) {
    asm volatile("mma.sync.aligned.m16n8k16.row.col.f32.f16.f16.f32 "
        "{%0,%1,%2,%3}, {%4,%5,%6,%7}, {%8,%9}, {%0,%1,%2,%3};"
        : "+f"(d[0]), "+f"(d[1]), "+f"(d[2]), "+f"(d[3])
        : "r"(a[0]), "r"(a[1]), "r"(a[2]), "r"(a[3]), "r"(b[0]), "r"(b[1]));
}
__device__ __forceinline__ float tanha(float x) {
    float y;
    asm("tanh.approx.f32 %0, %1;" : "=f"(y) : "f"(x));
    return y;
}
__device__ __forceinline__ void cp16(uint32_t dst, const void* src) {
    asm volatile("cp.async.cg.shared.global [%0], [%1], 16;"
                 :: "r"(dst), "l"(src) : "memory");
}
#define CP_COMMIT() asm volatile("cp.async.commit_group;" ::: "memory")
#define CP_WAIT(n)  asm volatile("cp.async.wait_group %0;" :: "n"(n) : "memory")

// ---------------- Kernel 1: qp[b,h] = query[b]·Wq[:,h] + bq[h] ----------------
__global__ void qp_kernel(const float* __restrict__ query,
                          const float* __restrict__ Wq,
                          const float* __restrict__ bq) {
    int b = blockIdx.x;
    int h = threadIdx.x;              // 512
    __shared__ float qs[QD];
    qs[h] = query[b*QD + h];
    __syncthreads();
    float acc = 0.f;
    #pragma unroll 8
    for (int v = 0; v < QD; v++) acc += qs[v] * Wq[v*HD + h];
    g_qp[b*HD + h] = acc + bq[h];
}

// ---------------- Kernel 1b: WkT[h][v] = fp16(Wk[v][h]) ----------------
__global__ void wkt_kernel(const float* __restrict__ Wk) {
    int h = blockIdx.x;
    int v = threadIdx.x;              // 512
    g_WkT[h*VD + v] = __float2half_rn(Wk[v*HD + h]);
}

// ---------------- Kernel 2: mma.sync score GEMM + fused tanh epilogue ---------
// CTA: 128 rows (flat b*S+s). A[128x512] fp16 in smem (pad 520), loaded once.
// h-tiles of 64 (8 tiles): B tile staged via cp.async, staging overlapped with
// the tanh epilogue of the previous tile. Warp grid 4M x 2N, ratio 8 MMA : 4 LDSM.
#define APAD 520
#define OFF_A   0
#define OFF_B   133120
#define OFF_QP  199680
#define OFF_WO  201728
#define OFF_RED 203776
#define SMEM_TOTAL (204288 + 256)

__device__ __forceinline__ void prefetch_b64(uint32_t bbase, int t, int tid) {
    const __half* src = g_WkT + (size_t)t * 64 * VD;
    #pragma unroll
    for (int it = 0; it < 16; it++) {
        int i = tid + it*256;         // 0..4095
        int n = i >> 6;               // row 0..63
        int g = i & 63;               // 16B chunk within row
        cp16(bbase + (uint32_t)(n*APAD + g*8)*2, src + (size_t)n*VD + g*8);
    }
}

__global__ __launch_bounds__(256, 1)
void score_mma_kernel(const float* __restrict__ value,
                      const float* __restrict__ Wo,
                      const float* __restrict__ bo) {
    extern __shared__ char sm[];
    const uint32_t sbase = smem_u32(sm);
    const int tid = threadIdx.x;
    const int L   = tid & 31;
    const int wid = tid >> 5;
    const int mw  = wid & 3;          // M-warp: rows mw*32..+31
    const int nw  = wid >> 2;         // N-warp: h-cols nw*32..+31 within tile
    const int b   = blockIdx.x >> 5;
    const size_t row0 = (size_t)blockIdx.x * 128;

    __half* As  = (__half*)(sm + OFF_A);
    float* qp_s = (float*)(sm + OFF_QP);
    float* wo_s = (float*)(sm + OFF_WO);
    float* red  = (float*)(sm + OFF_RED);

    // tile 0 B prefetch overlaps the A conversion below
    prefetch_b64(sbase + OFF_B, 0, tid);
    CP_COMMIT();

    // ---- stage A: value[row0..+127][0..511] f32 -> fp16, pad 520 ----
    {
        const float* vsrc = value + row0 * VD;
        #pragma unroll 4
        for (int it = 0; it < 64; it++) {
            int i  = tid + it*256;            // 0..16383
            int r  = i >> 7;
            int f4 = i & 127;
            float4 f = *(const float4*)(vsrc + (size_t)r*VD + f4*4);
            __half2 h0 = __floats2half2_rn(f.x, f.y);
            __half2 h1 = __floats2half2_rn(f.z, f.w);
            *(uint2*)(As + r*APAD + f4*4) =
                make_uint2(*(uint32_t*)&h0, *(uint32_t*)&h1);
        }
    }
    for (int i = tid; i < HD; i += 256) {
        qp_s[i] = g_qp[b*HD + i];
        wo_s[i] = Wo[i];
    }
    if (tid < 128) red[tid] = 0.f;

    // ldmatrix lane addresses (bytes)
    const uint32_t aAddr = sbase + OFF_A +
        (uint32_t)(((mw*32 + (L & 15))*APAD + (L >> 4)*8) * 2);
    const uint32_t bAddr = sbase + OFF_B +
        (uint32_t)(((nw*32 + (L & 7) + ((L >> 4) << 3))*APAD + ((L >> 3) & 1)*8) * 2);

    float sp[4] = {0.f, 0.f, 0.f, 0.f};      // per-lane score partials

    for (int t = 0; t < 8; t++) {
        CP_WAIT(0);                   // this thread's B[t] copies done
        __syncthreads();              // all threads' copies visible

        float acc[2][4][4];
        #pragma unroll
        for (int mi = 0; mi < 2; mi++)
            #pragma unroll
            for (int ni = 0; ni < 4; ni++)
                #pragma unroll
                for (int j = 0; j < 4; j++) acc[mi][ni][j] = 0.f;

        #pragma unroll 8
        for (int ks = 0; ks < 32; ks++) {
            const uint32_t kb = ks * 32;      // k16 step = 32 bytes
            uint32_t a0[4], a1[4], b0[4], b1[4];
            ldsm4(a0, aAddr + kb);
            ldsm4(a1, aAddr + 16*APAD*2 + kb);
            ldsm4(b0, bAddr + kb);
            ldsm4(b1, bAddr + 16*APAD*2 + kb);
            mma16816(acc[0][0], a0, b0 + 0);
            mma16816(acc[0][1], a0, b0 + 2);
            mma16816(acc[0][2], a0, b1 + 0);
            mma16816(acc[0][3], a0, b1 + 2);
            mma16816(acc[1][0], a1, b0 + 0);
            mma16816(acc[1][1], a1, b0 + 2);
            mma16816(acc[1][2], a1, b1 + 0);
            mma16816(acc[1][3], a1, b1 + 2);
        }

        __syncthreads();              // all warps done reading B[t]
        if (t < 7) {                  // start B[t+1]; overlaps epilogue below
            prefetch_b64(sbase + OFF_B, t + 1, tid);
            CP_COMMIT();
        }

        // ---- epilogue: sp += Wo[h] * tanh(acc + qp[h])  (no B access) ----
        #pragma unroll
        for (int ni = 0; ni < 4; ni++) {
            const int hb = t*64 + nw*32 + ni*8 + 2*(L & 3);
            const float qp0 = qp_s[hb],   qp1 = qp_s[hb + 1];
            const float wo0 = wo_s[hb],   wo1 = wo_s[hb + 1];
            #pragma unroll
            for (int mi = 0; mi < 2; mi++) {
                float t0 = tanha(acc[mi][ni][0] + qp0);
                float t1 = tanha(acc[mi][ni][1] + qp1);
                float t2 = tanha(acc[mi][ni][2] + qp0);
                float t3 = tanha(acc[mi][ni][3] + qp1);
                sp[mi*2 + 0] += wo0*t0 + wo1*t1;   // row mw*32 + mi*16 + L/4
                sp[mi*2 + 1] += wo0*t2 + wo1*t3;   // + 8
            }
        }
    }

    // reduce 4 lanes sharing a row, then combine 2 N-warps via smem atomics
    #pragma unroll
    for (int i = 0; i < 4; i++) {
        sp[i] += __shfl_xor_sync(0xffffffffu, sp[i], 1);
        sp[i] += __shfl_xor_sync(0xffffffffu, sp[i], 2);
    }
    if ((L & 3) == 0) {
        const int mr = mw*32 + (L >> 2);
        atomicAdd(&red[mr +  0], sp[0]);
        atomicAdd(&red[mr +  8], sp[1]);
        atomicAdd(&red[mr + 16], sp[2]);
        atomicAdd(&red[mr + 24], sp[3]);
    }
    __syncthreads();
    if (tid < 128)
        g_scores[row0 + tid] = red[tid] + bo[0];
}

// ---------------- Kernel 3: masked softmax, 512 thr, register-resident --------
__global__ __launch_bounds__(512)
void softmax_kernel(const int* __restrict__ mask,
                    float* __restrict__ att_out) {
    const int b = blockIdx.x;
    const int tid = threadIdx.x;      // 512
    const int L = tid & 31, w = tid >> 5;
    __shared__ float sred[16];

    float v[8];
    float m = -3.0e38f;
    #pragma unroll
    for (int i = 0; i < 8; i++) {
        int s = tid + i*512;
        float sc = (mask[b*SS + s] != 0) ? g_scores[b*SS + s] : -1e9f;
        v[i] = sc;
        m = fmaxf(m, sc);
    }
    #pragma unroll
    for (int off = 16; off > 0; off >>= 1)
        m = fmaxf(m, __shfl_xor_sync(0xffffffffu, m, off));
    if (L == 0) sred[w] = m;
    __syncthreads();
    if (w == 0) {
        float x = (L < 16) ? sred[L] : -3.0e38f;
        #pragma unroll
        for (int off = 8; off > 0; off >>= 1)
            x = fmaxf(x, __shfl_xor_sync(0xffffffffu, x, off));
        if (L == 0) sred[0] = x;
    }
    __syncthreads();
    m = sred[0];
    __syncthreads();

    float sum = 0.f;
    #pragma unroll
    for (int i = 0; i < 8; i++) {
        v[i] = expf(v[i] - m);
        sum += v[i];
    }
    #pragma unroll
    for (int off = 16; off > 0; off >>= 1)
        sum += __shfl_xor_sync(0xffffffffu, sum, off);
    if (L == 0) sred[w] = sum;
    __syncthreads();
    if (w == 0) {
        float x = (L < 16) ? sred[L] : 0.f;
        #pragma unroll
        for (int off = 8; off > 0; off >>= 1)
            x += __shfl_xor_sync(0xffffffffu, x, off);
        if (L == 0) sred[0] = x;
    }
    __syncthreads();
    const float inv = 1.f / sred[0];

    #pragma unroll
    for (int i = 0; i < 8; i++)
        att_out[b*SS + tid + i*512] = v[i] * inv;
}

// ---------------- Kernel 4: ctx partials ----------------
__global__ __launch_bounds__(128)
void ctx_part_kernel(const float* __restrict__ value,
                     const float* __restrict__ att) {
    __shared__ float atts[SS / CSPLIT];          // 128
    const int b = blockIdx.y, sc = blockIdx.x, t = threadIdx.x;
    const int s0 = sc * (SS / CSPLIT);

    atts[t] = att[b*SS + s0 + t];
    __syncthreads();

    const float* vb = value + ((size_t)(b*SS + s0))*VD + t*4;
    float ax = 0.f, ay = 0.f, az = 0.f, aw = 0.f;
    #pragma unroll 8
    for (int s = 0; s < SS / CSPLIT; s++) {
        float a = atts[s];
        float4 v4 = *(const float4*)(vb + (size_t)s*VD);
        ax = fmaf(a, v4.x, ax); ay = fmaf(a, v4.y, ay);
        az = fmaf(a, v4.z, az); aw = fmaf(a, v4.w, aw);
    }
    *(float4*)&g_cpart[((size_t)sc*BB + b)*VD + t*4] =
        make_float4(ax, ay, az, aw);
}

// ---------------- Kernel 5: reduce partials -> ctx ----------------
__global__ void ctx_reduce_kernel(float* __restrict__ ctx) {
    const int idx = blockIdx.x * 256 + threadIdx.x;  // 0..BB*VD-1
    float acc = 0.f;
    #pragma unroll
    for (int p = 0; p < CSPLIT; p++)
        acc += g_cpart[(size_t)p*(BB*VD) + idx];
    ctx[idx] = acc;
}

extern "C" void kernel_launch(void* const* d_in, const int* in_sizes, int n_in,
                              void* d_out, int out_size) {
    const float* query = (const float*)d_in[0];
    const float* value = (const float*)d_in[1];
    const int*   mask  = (const int*)d_in[2];   // bool promoted to int32
    const float* Wk    = (const float*)d_in[3];
    const float* Wq    = (const float*)d_in[4];
    const float* bq    = (const float*)d_in[5];
    const float* Wo    = (const float*)d_in[6];
    const float* bo    = (const float*)d_in[7];

    float* out = (float*)d_out;
    float* ctx = out;                 // [B, VD]
    float* att = out + CTX_SIZE;      // [B, S]

    qp_kernel<<<BB, 512>>>(query, Wq, bq);
    wkt_kernel<<<HD, VD>>>(Wk);

    cudaFuncSetAttribute(score_mma_kernel,
                         cudaFuncAttributeMaxDynamicSharedMemorySize, SMEM_TOTAL);
    score_mma_kernel<<<(BB*SS)/128, 256, SMEM_TOTAL>>>(value, Wo, bo);

    softmax_kernel<<<BB, 512>>>(mask, att);

    ctx_part_kernel<<<dim3(CSPLIT, BB), 128>>>(value, att);
    ctx_reduce_kernel<<<(BB*VD)/256, 256>>>(ctx);
}

// round 8
// speedup vs baseline: 1.1111x; 1.0231x over previous
#include <cuda_runtime.h>
#include <cuda_fp16.h>
#include <math.h>
#include <stdint.h>

#define BB 32
#define SS 4096
#define VD 512
#define HD 512
#define QD 512
#define CTX_SIZE (BB*VD)
#define CSPLIT 64

// -------- scratch (no allocation allowed) --------
__device__ float  g_qp[BB*HD];
__device__ float  g_scores[BB*SS];
__device__ float  g_cpart[CSPLIT*BB*VD];
__device__ __half g_WkT[HD*VD];   // [h][v] fp16 (B operand, K-major "col" layout)

// ---------------- helpers ----------------
__device__ __forceinline__ uint32_t smem_u32(const void* p) {
    uint32_t a;
    asm("{ .reg .u64 t; cvta.to.shared.u64 t, %1; cvt.u32.u64 %0, t; }"
        : "=r"(a) : "l"(p));
    return a;
}
__device__ __forceinline__ void ldsm4(uint32_t* r, uint32_t addr) {
    asm volatile("ldmatrix.sync.aligned.m8n8.x4.shared.b16 {%0,%1,%2,%3}, [%4];"
        : "=r"(r[0]), "=r"(r[1]), "=r"(r[2]), "=r"(r[3]) : "r"(addr));
}
__device__ __forceinline__ void mma16816(float* d, const uint32_t* a, const uint32_t* b) {
    asm volatile("mma.sync.aligned.m16n8k16.row.col.f32.f16.f16.f32 "
        "{%0,%1,%2,%3}, {%4,%5,%6,%7}, {%8,%9}, {%0,%1,%2,%3};"
        : "+f"(d[0]), "+f"(d[1]), "+f"(d[2]), "+f"(d[3])
        : "r"(a[0]), "r"(a[1]), "r"(a[2]), "r"(a[3]), "r"(b[0]), "r"(b[1]));
}
__device__ __forceinline__ float tanha(float x) {
    float y;
    asm("tanh.approx.f32 %0, %1;" : "=f"(y) : "f"(x));
    return y;
}
__device__ __forceinline__ void cp16(uint32_t dst, const void* src) {
    asm volatile("cp.async.cg.shared.global [%0], [%1], 16;"
                 :: "r"(dst), "l"(src) : "memory");
}
#define CP_COMMIT() asm volatile("cp.async.commit_group;" ::: "memory")
#define CP_WAIT(n)  asm volatile("cp.async.wait_group %0;" :: "n"(n) : "memory")

// ---------------- Kernel 1: fused prep ----------------
// blocks [0, HD):      WkT[h][v] = fp16(Wk[v][h])        (h = blockIdx.x)
// blocks [HD, HD+BB):  qp[b,h] = query[b]·Wq[:,h] + bq[h] (b = blockIdx.x - HD)
__global__ __launch_bounds__(512)
void prep_kernel(const float* __restrict__ query,
                 const float* __restrict__ Wq,
                 const float* __restrict__ bq,
                 const float* __restrict__ Wk) {
    if (blockIdx.x < HD) {
        int h = blockIdx.x;
        int v = threadIdx.x;          // 512
        g_WkT[h*VD + v] = __float2half_rn(Wk[v*HD + h]);
    } else {
        int b = blockIdx.x - HD;
        int h = threadIdx.x;          // 512
        __shared__ float qs[QD];
        qs[h] = query[b*QD + h];
        __syncthreads();
        float acc = 0.f;
        #pragma unroll 8
        for (int v = 0; v < QD; v++) acc += qs[v] * Wq[v*HD + h];
        g_qp[b*HD + h] = acc + bq[h];
    }
}

// ---------------- Kernel 2: mma.sync score GEMM + fused tanh epilogue ---------
// CTA: 128 rows. A[128x512] fp16 resident (pad 520). 8 B-tiles of 64 N via
// cp.async. k-loop software-pipelined: LDSM for ks+1 issued before HMMAs of ks.
#define APAD 520
#define OFF_A   0
#define OFF_B   133120
#define OFF_QP  199680
#define OFF_WO  201728
#define OFF_RED 203776
#define SMEM_TOTAL (204288 + 256)

__device__ __forceinline__ void prefetch_b64(uint32_t bbase, int t, int tid) {
    const __half* src = g_WkT + (size_t)t * 64 * VD;
    #pragma unroll
    for (int it = 0; it < 16; it++) {
        int i = tid + it*256;         // 0..4095
        int n = i >> 6;               // row 0..63
        int g = i & 63;               // 16B chunk within row
        cp16(bbase + (uint32_t)(n*APAD + g*8)*2, src + (size_t)n*VD + g*8);
    }
}

__global__ __launch_bounds__(256, 1)
void score_mma_kernel(const float* __restrict__ value,
                      const float* __restrict__ Wo,
                      const float* __restrict__ bo) {
    extern __shared__ char sm[];
    const uint32_t sbase = smem_u32(sm);
    const int tid = threadIdx.x;
    const int L   = tid & 31;
    const int wid = tid >> 5;
    const int mw  = wid & 3;          // M-warp: rows mw*32..+31
    const int nw  = wid >> 2;         // N-warp: h-cols nw*32..+31 within tile
    const int b   = blockIdx.x >> 5;
    const size_t row0 = (size_t)blockIdx.x * 128;

    __half* As  = (__half*)(sm + OFF_A);
    float* qp_s = (float*)(sm + OFF_QP);
    float* wo_s = (float*)(sm + OFF_WO);
    float* red  = (float*)(sm + OFF_RED);

    // tile 0 B prefetch overlaps the A conversion below
    prefetch_b64(sbase + OFF_B, 0, tid);
    CP_COMMIT();

    // ---- stage A: value[row0..+127][0..511] f32 -> fp16, pad 520 ----
    {
        const float* vsrc = value + row0 * VD;
        #pragma unroll 4
        for (int it = 0; it < 64; it++) {
            int i  = tid + it*256;            // 0..16383
            int r  = i >> 7;
            int f4 = i & 127;
            float4 f = *(const float4*)(vsrc + (size_t)r*VD + f4*4);
            __half2 h0 = __floats2half2_rn(f.x, f.y);
            __half2 h1 = __floats2half2_rn(f.z, f.w);
            *(uint2*)(As + r*APAD + f4*4) =
                make_uint2(*(uint32_t*)&h0, *(uint32_t*)&h1);
        }
    }
    for (int i = tid; i < HD; i += 256) {
        qp_s[i] = g_qp[b*HD + i];
        wo_s[i] = Wo[i];
    }
    if (tid < 128) red[tid] = 0.f;

    // ldmatrix lane addresses (bytes)
    const uint32_t aAddr = sbase + OFF_A +
        (uint32_t)(((mw*32 + (L & 15))*APAD + (L >> 4)*8) * 2);
    const uint32_t bAddr = sbase + OFF_B +
        (uint32_t)(((nw*32 + (L & 7) + ((L >> 4) << 3))*APAD + ((L >> 3) & 1)*8) * 2);

    float sp[4] = {0.f, 0.f, 0.f, 0.f};      // per-lane score partials

    for (int t = 0; t < 8; t++) {
        CP_WAIT(0);                   // this thread's B[t] copies done
        __syncthreads();              // all threads' copies visible

        float acc[2][4][4];
        #pragma unroll
        for (int mi = 0; mi < 2; mi++)
            #pragma unroll
            for (int ni = 0; ni < 4; ni++)
                #pragma unroll
                for (int j = 0; j < 4; j++) acc[mi][ni][j] = 0.f;

        // ---- software-pipelined k-loop: frags for ks+1 load under MMAs of ks
        uint32_t fA0[2][4], fA1[2][4], fB0[2][4], fB1[2][4];
        ldsm4(fA0[0], aAddr);
        ldsm4(fA1[0], aAddr + 16*APAD*2);
        ldsm4(fB0[0], bAddr);
        ldsm4(fB1[0], bAddr + 16*APAD*2);

        #pragma unroll
        for (int ks = 0; ks < 32; ks++) {
            const int cur = ks & 1, nxt = cur ^ 1;
            if (ks < 31) {
                const uint32_t kb = (uint32_t)(ks + 1) * 32;
                ldsm4(fA0[nxt], aAddr + kb);
                ldsm4(fA1[nxt], aAddr + 16*APAD*2 + kb);
                ldsm4(fB0[nxt], bAddr + kb);
                ldsm4(fB1[nxt], bAddr + 16*APAD*2 + kb);
            }
            mma16816(acc[0][0], fA0[cur], fB0[cur] + 0);
            mma16816(acc[0][1], fA0[cur], fB0[cur] + 2);
            mma16816(acc[0][2], fA0[cur], fB1[cur] + 0);
            mma16816(acc[0][3], fA0[cur], fB1[cur] + 2);
            mma16816(acc[1][0], fA1[cur], fB0[cur] + 0);
            mma16816(acc[1][1], fA1[cur], fB0[cur] + 2);
            mma16816(acc[1][2], fA1[cur], fB1[cur] + 0);
            mma16816(acc[1][3], fA1[cur], fB1[cur] + 2);
        }

        __syncthreads();              // all warps done reading B[t]
        if (t < 7) {                  // start B[t+1]; overlaps epilogue below
            prefetch_b64(sbase + OFF_B, t + 1, tid);
            CP_COMMIT();
        }

        // ---- epilogue: sp += Wo[h] * tanh(acc + qp[h])  (no B access) ----
        #pragma unroll
        for (int ni = 0; ni < 4; ni++) {
            const int hb = t*64 + nw*32 + ni*8 + 2*(L & 3);
            const float qp0 = qp_s[hb],   qp1 = qp_s[hb + 1];
            const float wo0 = wo_s[hb],   wo1 = wo_s[hb + 1];
            #pragma unroll
            for (int mi = 0; mi < 2; mi++) {
                float t0 = tanha(acc[mi][ni][0] + qp0);
                float t1 = tanha(acc[mi][ni][1] + qp1);
                float t2 = tanha(acc[mi][ni][2] + qp0);
                float t3 = tanha(acc[mi][ni][3] + qp1);
                sp[mi*2 + 0] += wo0*t0 + wo1*t1;   // row mw*32 + mi*16 + L/4
                sp[mi*2 + 1] += wo0*t2 + wo1*t3;   // + 8
            }
        }
    }

    // reduce 4 lanes sharing a row, then combine 2 N-warps via smem atomics
    #pragma unroll
    for (int i = 0; i < 4; i++) {
        sp[i] += __shfl_xor_sync(0xffffffffu, sp[i], 1);
        sp[i] += __shfl_xor_sync(0xffffffffu, sp[i], 2);
    }
    if ((L & 3) == 0) {
        const int mr = mw*32 + (L >> 2);
        atomicAdd(&red[mr +  0], sp[0]);
        atomicAdd(&red[mr +  8], sp[1]);
        atomicAdd(&red[mr + 16], sp[2]);
        atomicAdd(&red[mr + 24], sp[3]);
    }
    __syncthreads();
    if (tid < 128)
        g_scores[row0 + tid] = red[tid] + bo[0];
}

// ---------------- Kernel 3: masked softmax, 512 thr, register-resident --------
__global__ __launch_bounds__(512)
void softmax_kernel(const int* __restrict__ mask,
                    float* __restrict__ att_out) {
    const int b = blockIdx.x;
    const int tid = threadIdx.x;      // 512
    const int L = tid & 31, w = tid >> 5;
    __shared__ float sred[16];

    float v[8];
    float m = -3.0e38f;
    #pragma unroll
    for (int i = 0; i < 8; i++) {
        int s = tid + i*512;
        float sc = (mask[b*SS + s] != 0) ? g_scores[b*SS + s] : -1e9f;
        v[i] = sc;
        m = fmaxf(m, sc);
    }
    #pragma unroll
    for (int off = 16; off > 0; off >>= 1)
        m = fmaxf(m, __shfl_xor_sync(0xffffffffu, m, off));
    if (L == 0) sred[w] = m;
    __syncthreads();
    if (w == 0) {
        float x = (L < 16) ? sred[L] : -3.0e38f;
        #pragma unroll
        for (int off = 8; off > 0; off >>= 1)
            x = fmaxf(x, __shfl_xor_sync(0xffffffffu, x, off));
        if (L == 0) sred[0] = x;
    }
    __syncthreads();
    m = sred[0];
    __syncthreads();

    float sum = 0.f;
    #pragma unroll
    for (int i = 0; i < 8; i++) {
        v[i] = expf(v[i] - m);
        sum += v[i];
    }
    #pragma unroll
    for (int off = 16; off > 0; off >>= 1)
        sum += __shfl_xor_sync(0xffffffffu, sum, off);
    if (L == 0) sred[w] = sum;
    __syncthreads();
    if (w == 0) {
        float x = (L < 16) ? sred[L] : 0.f;
        #pragma unroll
        for (int off = 8; off > 0; off >>= 1)
            x += __shfl_xor_sync(0xffffffffu, x, off);
        if (L == 0) sred[0] = x;
    }
    __syncthreads();
    const float inv = 1.f / sred[0];

    #pragma unroll
    for (int i = 0; i < 8; i++)
        att_out[b*SS + tid + i*512] = v[i] * inv;
}

// ---------------- Kernel 4: ctx partials ----------------
__global__ __launch_bounds__(128)
void ctx_part_kernel(const float* __restrict__ value,
                     const float* __restrict__ att) {
    __shared__ float atts[SS / CSPLIT];          // 64
    const int b = blockIdx.y, sc = blockIdx.x, t = threadIdx.x;
    const int s0 = sc * (SS / CSPLIT);

    if (t < SS / CSPLIT) atts[t] = att[b*SS + s0 + t];
    __syncthreads();

    const float* vb = value + ((size_t)(b*SS + s0))*VD + t*4;
    float ax = 0.f, ay = 0.f, az = 0.f, aw = 0.f;
    #pragma unroll 8
    for (int s = 0; s < SS / CSPLIT; s++) {
        float a = atts[s];
        float4 v4 = *(const float4*)(vb + (size_t)s*VD);
        ax = fmaf(a, v4.x, ax); ay = fmaf(a, v4.y, ay);
        az = fmaf(a, v4.z, az); aw = fmaf(a, v4.w, aw);
    }
    *(float4*)&g_cpart[((size_t)sc*BB + b)*VD + t*4] =
        make_float4(ax, ay, az, aw);
}

// ---------------- Kernel 5: reduce partials -> ctx ----------------
__global__ void ctx_reduce_kernel(float* __restrict__ ctx) {
    const int idx = blockIdx.x * 256 + threadIdx.x;  // 0..BB*VD-1
    float acc = 0.f;
    #pragma unroll
    for (int p = 0; p < CSPLIT; p++)
        acc += g_cpart[(size_t)p*(BB*VD) + idx];
    ctx[idx] = acc;
}

extern "C" void kernel_launch(void* const* d_in, const int* in_sizes, int n_in,
                              void* d_out, int out_size) {
    const float* query = (const float*)d_in[0];
    const float* value = (const float*)d_in[1];
    const int*   mask  = (const int*)d_in[2];   // bool promoted to int32
    const float* Wk    = (const float*)d_in[3];
    const float* Wq    = (const float*)d_in[4];
    const float* bq    = (const float*)d_in[5];
    const float* Wo    = (const float*)d_in[6];
    const float* bo    = (const float*)d_in[7];

    float* out = (float*)d_out;
    float* ctx = out;                 // [B, VD]
    float* att = out + CTX_SIZE;      // [B, S]

    prep_kernel<<<HD + BB, 512>>>(query, Wq, bq, Wk);

    cudaFuncSetAttribute(score_mma_kernel,
                         cudaFuncAttributeMaxDynamicSharedMemorySize, SMEM_TOTAL);
    score_mma_kernel<<<(BB*SS)/128, 256, SMEM_TOTAL>>>(value, Wo, bo);

    softmax_kernel<<<BB, 512>>>(mask, att);

    ctx_part_kernel<<<dim3(CSPLIT, BB), 128>>>(value, att);
    ctx_reduce_kernel<<<(BB*VD)/256, 256>>>(ctx);
}